// round 11
// baseline (speedup 1.0000x reference)
#include <cuda_runtime.h>
#include <cuda_fp16.h>

#define NV   6
#define C    16
#define IMH  480
#define IMW  640
#define DVOL 96
#define PVOX (DVOL*DVOL*DVOL)
#define HW   (IMH*IMW)
#define BLKS_PER_VIEW (HW / 256)   // 1200; blocks never straddle views

// Channel-packed fp16 feature scratch: (v, y, x, c), 16 halves = 32B/pixel (2x uint4).
__device__ uint4 g_feat[(size_t)NV * HW * 2];

// ---------------------------------------------------------------------------
// Per-view projection build: P = K(3x4) @ w2c(4x4), w2c = [R^T, -R^T t].
// ---------------------------------------------------------------------------
__device__ __forceinline__ void build_view_matrix(const float* __restrict__ intrs,
                                                  const float* __restrict__ c2ws,
                                                  int v, float* __restrict__ dstM) {
    const float* cm = c2ws + v * 16;
    float R[9], t[3];
#pragma unroll
    for (int r = 0; r < 3; r++) {
#pragma unroll
        for (int c = 0; c < 3; c++) R[r * 3 + c] = cm[r * 4 + c];
        t[r] = cm[r * 4 + 3];
    }
    float w2c[12];
#pragma unroll
    for (int r = 0; r < 3; r++) {
#pragma unroll
        for (int c = 0; c < 3; c++) w2c[r * 4 + c] = R[c * 3 + r];  // R^T
        w2c[r * 4 + 3] = -(R[0 * 3 + r] * t[0] + R[1 * 3 + r] * t[1] + R[2 * 3 + r] * t[2]);
    }
    const float* K = intrs + v * 12;
#pragma unroll
    for (int r = 0; r < 3; r++) {
#pragma unroll
        for (int c = 0; c < 4; c++) {
            float s = 0.f;
#pragma unroll
            for (int k = 0; k < 3; k++) s += K[r * 4 + k] * w2c[k * 4 + c];
            if (c == 3) s += K[r * 4 + 3];
            dstM[r * 4 + c] = s;
        }
    }
}

// ---------------------------------------------------------------------------
// Transpose + fp16 pack, cropped to the columns actually sampled.
// The cube [-1,1]^3 is fully in front of every camera, so its projection is
// the convex hull of the 8 projected corners; columns outside that hull's
// x-range (+-2px margin for bilinear + fp noise) are never read by vol_kernel.
// ---------------------------------------------------------------------------
__global__ __launch_bounds__(256) void transpose_kernel(const float* __restrict__ feat,
                                                        const float* __restrict__ intrs,
                                                        const float* __restrict__ c2ws) {
    __shared__ int s_xlo, s_xhi;
    const int v = blockIdx.x / BLKS_PER_VIEW;

    if (threadIdx.x == 0) {
        float M[12];
        build_view_matrix(intrs, c2ws, v, M);
        float xmin = 1e30f, xmax = -1e30f;
        bool safe = true;
#pragma unroll
        for (int c = 0; c < 8; c++) {
            float wx = (c & 1) ? 1.f : -1.f;
            float wy = (c & 2) ? 1.f : -1.f;
            float wz = (c & 4) ? 1.f : -1.f;
            float px = M[0] * wx + M[1] * wy + M[2]  * wz + M[3];
            float pz = M[8] * wx + M[9] * wy + M[10] * wz + M[11];
            if (pz <= 1e-6f) { safe = false; break; }
            float sx = px / (pz + 1e-8f);
            xmin = fminf(xmin, sx);
            xmax = fmaxf(xmax, sx);
        }
        if (safe) {
            s_xlo = max(0, (int)floorf(xmin) - 2);
            s_xhi = min(IMW - 1, (int)ceilf(xmax) + 2);
        } else {            // corner behind camera: conservative full range
            s_xlo = 0;
            s_xhi = IMW - 1;
        }
    }
    __syncthreads();

    const int p = blockIdx.x * 256 + threadIdx.x;   // pixel id in [0, NV*HW)
    const int pix = p - v * HW;
    const int col = pix % IMW;
    if (col < s_xlo || col > s_xhi) return;          // never sampled -> skip

    const float* base = feat + (size_t)v * C * HW + pix;
    float f[C];
#pragma unroll
    for (int ch = 0; ch < C; ch++) f[ch] = __ldcs(base + (size_t)ch * HW);

    __half2 h[8];
#pragma unroll
    for (int r = 0; r < 8; r++) h[r] = __floats2half2_rn(f[2 * r], f[2 * r + 1]);

    uint4* dst = g_feat + (size_t)p * 2;
    const uint4* hu = (const uint4*)h;
    dst[0] = hu[0];
    dst[1] = hu[1];
}

// ---------------------------------------------------------------------------
// Main volume kernel: one thread per voxel, HFMA2 bilinear blend.
// min 4 CTAs/SM (<=64 regs) for gather-latency hiding (measured 20.8us).
// ---------------------------------------------------------------------------
__global__ __launch_bounds__(256, 4) void vol_kernel(float* __restrict__ out,
                                                     const float* __restrict__ intrs,
                                                     const float* __restrict__ c2ws) {
    __shared__ float sM[NV * 12];
    {
        int tid = threadIdx.y * 32 + threadIdx.x;
        if (tid < NV) build_view_matrix(intrs, c2ws, tid, sM + tid * 12);
    }
    __syncthreads();

    const int k = blockIdx.x * 32 + threadIdx.x;
    const int j = blockIdx.y * 8 + threadIdx.y;
    const int i = blockIdx.z;

    const float step = 2.0f / (DVOL - 1);
    const float wx = -1.0f + i * step;
    const float wy = -1.0f + j * step;
    const float wz = -1.0f + k * step;

    float sum[C], sq[C];
#pragma unroll
    for (int ch = 0; ch < C; ch++) { sum[ch] = 0.f; sq[ch] = 0.f; }
    float cnt = 0.f;

#pragma unroll
    for (int v = 0; v < NV; v++) {
        const float* M = sM + v * 12;
        float px = M[0] * wx + M[1] * wy + M[2]  * wz + M[3];
        float py = M[4] * wx + M[5] * wy + M[6]  * wz + M[7];
        float pz = M[8] * wx + M[9] * wy + M[10] * wz + M[11];
        float zb = pz + 1e-8f;
        // division-free frustum test: for zb>0, |nx|<=1 <=> 0 <= px <= (W-1)*zb
        bool ok = (pz > 0.0f) &&
                  (px >= 0.0f) && (px <= (IMW - 1) * zb) &&
                  (py >= 0.0f) && (py <= (IMH - 1) * zb);
        if (!ok) continue;

        float invz = 1.0f / zb;
        float sx = px * invz, sy = py * invz;
        // mirror reference op order for the sample position
        float nx = sx / ((IMW - 1) * 0.5f) - 1.0f;
        float ny = sy / ((IMH - 1) * 0.5f) - 1.0f;
        float ix = (nx + 1.0f) * 0.5f * (IMW - 1);   // in [0, W-1]
        float iy = (ny + 1.0f) * 0.5f * (IMH - 1);   // in [0, H-1]
        // ix,iy >= 0 here, so trunc == floor; corner 0 always in-bounds.
        int x0 = (int)ix, y0 = (int)iy;
        float wx1 = ix - (float)x0, wy1 = iy - (float)y0;
        float wx0f = 1.0f - wx1, wy0f = 1.0f - wy1;
        bool vx1 = (x0 + 1) < IMW;
        bool vy1 = (y0 + 1) < IMH;
        float w00 = wx0f * wy0f;
        float w10 = vx1 ? wx1 * wy0f : 0.f;
        float w01 = vy1 ? wx0f * wy1 : 0.f;
        float w11 = (vx1 & vy1) ? wx1 * wy1 : 0.f;
        int xs = vx1 ? 2 : 0;                // +1-corner pixel stride in uint4 units
        int r0 = y0 * IMW + x0;
        int r1 = vy1 ? r0 + IMW : r0;

        __half2 h00 = __float2half2_rn(w00);
        __half2 h10 = __float2half2_rn(w10);
        __half2 h01 = __float2half2_rn(w01);
        __half2 h11 = __float2half2_rn(w11);

        const uint4* fb = g_feat + (size_t)v * HW * 2;
        int b00 = r0 * 2;
        int b10 = r0 * 2 + xs;
        int b01 = r1 * 2;
        int b11 = r1 * 2 + xs;

        cnt += 1.0f;
#pragma unroll
        for (int q = 0; q < 2; q++) {
            uint4 u00 = __ldg(fb + b00 + q);
            uint4 u10 = __ldg(fb + b10 + q);
            uint4 u01 = __ldg(fb + b01 + q);
            uint4 u11 = __ldg(fb + b11 + q);
            const __half2* p00 = (const __half2*)&u00;
            const __half2* p10 = (const __half2*)&u10;
            const __half2* p01 = (const __half2*)&u01;
            const __half2* p11 = (const __half2*)&u11;
#pragma unroll
            for (int r = 0; r < 4; r++) {
                __half2 acc = __hmul2(p00[r], h00);
                acc = __hfma2(p10[r], h10, acc);
                acc = __hfma2(p01[r], h01, acc);
                acc = __hfma2(p11[r], h11, acc);
                float2 a = __half22float2(acc);
                int ch = q * 8 + r * 2;
                sum[ch]     += a.x;  sq[ch]     += a.x * a.x;
                sum[ch + 1] += a.y;  sq[ch + 1] += a.y * a.y;
            }
        }
    }

    const size_t idx = (size_t)i * DVOL * DVOL + (size_t)j * DVOL + k;
    const float rinv = 1.0f / ((cnt <= 0.f) ? 1e-8f : cnt);
    // streaming stores: single-touch output must not evict features from L2
#pragma unroll
    for (int ch = 0; ch < C; ch++) {
        float mean = sum[ch] * rinv;
        float var  = sq[ch] * rinv - mean * mean;
        __stcs(out + (size_t)ch * PVOX + idx, mean);
        __stcs(out + (size_t)(C + ch) * PVOX + idx, var);
    }
    __stcs(out + (size_t)(2 * C) * PVOX + idx, (cnt > 1.0f) ? 1.0f : 0.0f);  // MIN_VIS_VIEW=1
}

// ---------------------------------------------------------------------------
extern "C" void kernel_launch(void* const* d_in, const int* in_sizes, int n_in,
                              void* d_out, int out_size) {
    const float* feat  = (const float*)d_in[0];  // (6,16,480,640)
    const float* intrs = (const float*)d_in[1];  // (6,3,4)
    const float* c2ws  = (const float*)d_in[2];  // (6,4,4)
    float* out = (float*)d_out;                  // 32*P + P fp32

    int npix = NV * HW;
    transpose_kernel<<<npix / 256, 256>>>(feat, intrs, c2ws);

    dim3 blk(32, 8, 1);
    dim3 grd(DVOL / 32, DVOL / 8, DVOL);
    vol_kernel<<<grd, blk>>>(out, intrs, c2ws);
}

// round 14
// speedup vs baseline: 1.0419x; 1.0419x over previous
#include <cuda_runtime.h>
#include <cuda_fp16.h>

#define NV   6
#define C    16
#define IMH  480
#define IMW  640
#define DVOL 96
#define PVOX (DVOL*DVOL*DVOL)
#define HW   (IMH*IMW)

// Split channel-packed fp16 scratch (SoA): lo = channels 0-7, hi = channels 8-15.
// 16B/pixel per plane -> warp gather lanes stride 16B: ~2x denser L1 lines
// than the interleaved 32B/pixel layout.
__device__ uint4 g_feat_lo[(size_t)NV * HW];
__device__ uint4 g_feat_hi[(size_t)NV * HW];

// ---------------------------------------------------------------------------
// Per-view projection build: P = K(3x4) @ w2c(4x4), w2c = [R^T, -R^T t].
// ---------------------------------------------------------------------------
__device__ __forceinline__ void build_view_matrix(const float* __restrict__ intrs,
                                                  const float* __restrict__ c2ws,
                                                  int v, float* __restrict__ dstM) {
    const float* cm = c2ws + v * 16;
    float R[9], t[3];
#pragma unroll
    for (int r = 0; r < 3; r++) {
#pragma unroll
        for (int c = 0; c < 3; c++) R[r * 3 + c] = cm[r * 4 + c];
        t[r] = cm[r * 4 + 3];
    }
    float w2c[12];
#pragma unroll
    for (int r = 0; r < 3; r++) {
#pragma unroll
        for (int c = 0; c < 3; c++) w2c[r * 4 + c] = R[c * 3 + r];  // R^T
        w2c[r * 4 + 3] = -(R[0 * 3 + r] * t[0] + R[1 * 3 + r] * t[1] + R[2 * 3 + r] * t[2]);
    }
    const float* K = intrs + v * 12;
#pragma unroll
    for (int r = 0; r < 3; r++) {
#pragma unroll
        for (int c = 0; c < 4; c++) {
            float s = 0.f;
#pragma unroll
            for (int k = 0; k < 3; k++) s += K[r * 4 + k] * w2c[k * 4 + c];
            if (c == 3) s += K[r * 4 + 3];
            dstM[r * 4 + c] = s;
        }
    }
}

// ---------------------------------------------------------------------------
// Transpose + fp16 pack (1 pixel/thread, known-good): planar fp32 -> split SoA half.
// Loads: 16 coalesced LDG.32; Stores: 2 STG.128 at 16B lane stride (fully-covered lines).
// ---------------------------------------------------------------------------
__global__ __launch_bounds__(256) void transpose_kernel(const float* __restrict__ feat) {
    int p = blockIdx.x * blockDim.x + threadIdx.x;  // pixel id in [0, NV*HW)
    if (p >= NV * HW) return;
    int v = p / HW;
    int pix = p - v * HW;
    const float* base = feat + (size_t)v * C * HW + pix;

    float f[C];
#pragma unroll
    for (int ch = 0; ch < C; ch++) f[ch] = __ldcs(base + (size_t)ch * HW);

    __half2 h[8];
#pragma unroll
    for (int r = 0; r < 8; r++) h[r] = __floats2half2_rn(f[2 * r], f[2 * r + 1]);

    const uint4* hu = (const uint4*)h;
    g_feat_lo[p] = hu[0];
    g_feat_hi[p] = hu[1];
}

// ---------------------------------------------------------------------------
// Main volume kernel: one thread per voxel, HFMA2 bilinear blend, split-plane gathers.
// min 4 CTAs/SM (<=64 regs) for gather-latency hiding.
// ---------------------------------------------------------------------------
__global__ __launch_bounds__(256, 4) void vol_kernel(float* __restrict__ out,
                                                     const float* __restrict__ intrs,
                                                     const float* __restrict__ c2ws) {
    __shared__ float sM[NV * 12];
    {
        int tid = threadIdx.y * 32 + threadIdx.x;
        if (tid < NV) build_view_matrix(intrs, c2ws, tid, sM + tid * 12);
    }
    __syncthreads();

    const int k = blockIdx.x * 32 + threadIdx.x;
    const int j = blockIdx.y * 8 + threadIdx.y;
    const int i = blockIdx.z;

    const float step = 2.0f / (DVOL - 1);
    const float wx = -1.0f + i * step;
    const float wy = -1.0f + j * step;
    const float wz = -1.0f + k * step;

    float sum[C], sq[C];
#pragma unroll
    for (int ch = 0; ch < C; ch++) { sum[ch] = 0.f; sq[ch] = 0.f; }
    float cnt = 0.f;

#pragma unroll
    for (int v = 0; v < NV; v++) {
        const float* M = sM + v * 12;
        float px = M[0] * wx + M[1] * wy + M[2]  * wz + M[3];
        float py = M[4] * wx + M[5] * wy + M[6]  * wz + M[7];
        float pz = M[8] * wx + M[9] * wy + M[10] * wz + M[11];
        float zb = pz + 1e-8f;
        // division-free frustum test: for zb>0, |nx|<=1 <=> 0 <= px <= (W-1)*zb
        bool ok = (pz > 0.0f) &&
                  (px >= 0.0f) && (px <= (IMW - 1) * zb) &&
                  (py >= 0.0f) && (py <= (IMH - 1) * zb);
        if (!ok) continue;

        float invz = 1.0f / zb;
        float sx = px * invz, sy = py * invz;
        // mirror reference op order for the sample position
        float nx = sx / ((IMW - 1) * 0.5f) - 1.0f;
        float ny = sy / ((IMH - 1) * 0.5f) - 1.0f;
        float ix = (nx + 1.0f) * 0.5f * (IMW - 1);   // in [0, W-1]
        float iy = (ny + 1.0f) * 0.5f * (IMH - 1);   // in [0, H-1]
        // ix,iy >= 0 here, so trunc == floor; corner 0 always in-bounds.
        int x0 = (int)ix, y0 = (int)iy;
        float wx1 = ix - (float)x0, wy1 = iy - (float)y0;
        float wx0f = 1.0f - wx1, wy0f = 1.0f - wy1;
        bool vx1 = (x0 + 1) < IMW;
        bool vy1 = (y0 + 1) < IMH;
        float w00 = wx0f * wy0f;
        float w10 = vx1 ? wx1 * wy0f : 0.f;
        float w01 = vy1 ? wx0f * wy1 : 0.f;
        float w11 = (vx1 & vy1) ? wx1 * wy1 : 0.f;
        int xs = vx1 ? 1 : 0;                // +1-corner pixel stride
        int o00 = y0 * IMW + x0;
        int o01 = vy1 ? o00 + IMW : o00;
        int o10 = o00 + xs;
        int o11 = o01 + xs;

        __half2 h00 = __float2half2_rn(w00);
        __half2 h10 = __float2half2_rn(w10);
        __half2 h01 = __float2half2_rn(w01);
        __half2 h11 = __float2half2_rn(w11);

        const uint4* flo = g_feat_lo + (size_t)v * HW;
        const uint4* fhi = g_feat_hi + (size_t)v * HW;

        cnt += 1.0f;
#pragma unroll
        for (int q = 0; q < 2; q++) {
            const uint4* fb = q ? fhi : flo;
            uint4 u00 = __ldg(fb + o00);
            uint4 u10 = __ldg(fb + o10);
            uint4 u01 = __ldg(fb + o01);
            uint4 u11 = __ldg(fb + o11);
            const __half2* p00 = (const __half2*)&u00;
            const __half2* p10 = (const __half2*)&u10;
            const __half2* p01 = (const __half2*)&u01;
            const __half2* p11 = (const __half2*)&u11;
#pragma unroll
            for (int r = 0; r < 4; r++) {
                __half2 acc = __hmul2(p00[r], h00);
                acc = __hfma2(p10[r], h10, acc);
                acc = __hfma2(p01[r], h01, acc);
                acc = __hfma2(p11[r], h11, acc);
                float2 a = __half22float2(acc);
                int ch = q * 8 + r * 2;
                sum[ch]     += a.x;  sq[ch]     += a.x * a.x;
                sum[ch + 1] += a.y;  sq[ch + 1] += a.y * a.y;
            }
        }
    }

    const size_t idx = (size_t)i * DVOL * DVOL + (size_t)j * DVOL + k;
    const float rinv = 1.0f / ((cnt <= 0.f) ? 1e-8f : cnt);
    // streaming stores: single-touch output must not evict features from L2
#pragma unroll
    for (int ch = 0; ch < C; ch++) {
        float mean = sum[ch] * rinv;
        float var  = sq[ch] * rinv - mean * mean;
        __stcs(out + (size_t)ch * PVOX + idx, mean);
        __stcs(out + (size_t)(C + ch) * PVOX + idx, var);
    }
    __stcs(out + (size_t)(2 * C) * PVOX + idx, (cnt > 1.0f) ? 1.0f : 0.0f);  // MIN_VIS_VIEW=1
}

// ---------------------------------------------------------------------------
extern "C" void kernel_launch(void* const* d_in, const int* in_sizes, int n_in,
                              void* d_out, int out_size) {
    const float* feat  = (const float*)d_in[0];  // (6,16,480,640)
    const float* intrs = (const float*)d_in[1];  // (6,3,4)
    const float* c2ws  = (const float*)d_in[2];  // (6,4,4)
    float* out = (float*)d_out;                  // 32*P + P fp32

    int npix = NV * HW;
    transpose_kernel<<<(npix + 255) / 256, 256>>>(feat);

    dim3 blk(32, 8, 1);
    dim3 grd(DVOL / 32, DVOL / 8, DVOL);
    vol_kernel<<<grd, blk>>>(out, intrs, c2ws);
}